// round 5
// baseline (speedup 1.0000x reference)
#include <cuda_runtime.h>

#define EMBED 1024
#define NHEAD 16
#define HDIM  64
#define BATCH 2
#define SEQ   2048
#define MROWS (BATCH*SEQ)   /* 4096 */
#define NEGV  (-1e20f)

/* ------------ scratch (device globals; no allocation allowed) ------------ */
__device__ float g_Q[MROWS*EMBED];
__device__ float g_K[MROWS*EMBED];
__device__ float g_V[MROWS*EMBED];
__device__ float g_C[MROWS*EMBED];

/* ------------ packed f32x2 helpers (FFMA2 path, bit-exact fp32) ---------- */
__device__ __forceinline__ unsigned long long pk2(float lo, float hi) {
    unsigned long long r;
    asm("mov.b64 %0, {%1,%2};" : "=l"(r) : "f"(lo), "f"(hi));
    return r;
}
__device__ __forceinline__ void fma2(unsigned long long& d,
                                     unsigned long long a, unsigned long long b) {
    asm("fma.rn.f32x2 %0, %1, %2, %0;" : "+l"(d) : "l"(a), "l"(b));
}
__device__ __forceinline__ void mul2(unsigned long long& d, unsigned long long a) {
    asm("mul.rn.f32x2 %0, %0, %1;" : "+l"(d) : "l"(a));
}
__device__ __forceinline__ float2 up2(unsigned long long v) {
    float2 f;
    asm("mov.b64 {%0,%1}, %2;" : "=f"(f.x), "=f"(f.y) : "l"(v));
    return f;
}

/* ========================================================================
 *  NT GEMM: Y[m,n] = sum_k X[m,k] * W[n,k] (+ bias[n])
 *  M=4096 (or caller-tiled), N=K=1024 fixed. BM=BN=128, BK=32.
 *  256 threads, 8x8 thread tile, f32x2 accumulators.
 * ======================================================================== */
#define BKg  32
#define GPAD 132

__device__ __forceinline__ void gemm_nt_tile(const float* __restrict__ X,
                                             const float* __restrict__ W,
                                             const float* __restrict__ bias,
                                             float* __restrict__ Y)
{
    __shared__ __align__(16) float As[BKg][GPAD];   /* As[k][m] */
    __shared__ __align__(16) float Bs[BKg][GPAD];   /* Bs[k][n] */

    const int tid = threadIdx.x;
    const int m0  = blockIdx.y * 128;
    const int n0  = blockIdx.x * 128;
    const int lr  = tid >> 3;          /* 0..31 */
    const int lc  = (tid & 7) << 2;    /* 0,4,..,28 */
    const int tx  = tid & 15;
    const int ty  = tid >> 4;

    unsigned long long acc[8][4];
#pragma unroll
    for (int i = 0; i < 8; i++)
#pragma unroll
        for (int j = 0; j < 4; j++) acc[i][j] = 0ull;

    for (int k0 = 0; k0 < EMBED; k0 += BKg) {
        __syncthreads();
#pragma unroll
        for (int p = 0; p < 4; p++) {
            int m = lr + p * 32;
            float4 vx = *(const float4*)(X + (size_t)(m0 + m) * EMBED + k0 + lc);
            As[lc + 0][m] = vx.x; As[lc + 1][m] = vx.y;
            As[lc + 2][m] = vx.z; As[lc + 3][m] = vx.w;
            float4 vw = *(const float4*)(W + (size_t)(n0 + m) * EMBED + k0 + lc);
            Bs[lc + 0][m] = vw.x; Bs[lc + 1][m] = vw.y;
            Bs[lc + 2][m] = vw.z; Bs[lc + 3][m] = vw.w;
        }
        __syncthreads();

#pragma unroll 8
        for (int kk = 0; kk < BKg; kk++) {
            float4 a0 = *(const float4*)&As[kk][ty * 8];
            float4 a1 = *(const float4*)&As[kk][ty * 8 + 4];
            ulonglong2 b0 = *(const ulonglong2*)&Bs[kk][tx * 8];
            ulonglong2 b1 = *(const ulonglong2*)&Bs[kk][tx * 8 + 4];
            float av[8] = {a0.x, a0.y, a0.z, a0.w, a1.x, a1.y, a1.z, a1.w};
#pragma unroll
            for (int i = 0; i < 8; i++) {
                unsigned long long ad = pk2(av[i], av[i]);
                fma2(acc[i][0], ad, b0.x);
                fma2(acc[i][1], ad, b0.y);
                fma2(acc[i][2], ad, b1.x);
                fma2(acc[i][3], ad, b1.y);
            }
        }
    }

    const int n = n0 + tx * 8;
#pragma unroll
    for (int i = 0; i < 8; i++) {
        float2 c0 = up2(acc[i][0]), c1 = up2(acc[i][1]);
        float2 c2 = up2(acc[i][2]), c3 = up2(acc[i][3]);
        float4 o0 = make_float4(c0.x, c0.y, c1.x, c1.y);
        float4 o1 = make_float4(c2.x, c2.y, c3.x, c3.y);
        if (bias) {
            float4 bb0 = *(const float4*)(bias + n);
            float4 bb1 = *(const float4*)(bias + n + 4);
            o0.x += bb0.x; o0.y += bb0.y; o0.z += bb0.z; o0.w += bb0.w;
            o1.x += bb1.x; o1.y += bb1.y; o1.z += bb1.z; o1.w += bb1.w;
        }
        float* yp = Y + (size_t)(m0 + ty * 8 + i) * EMBED + n;
        *(float4*)yp       = o0;
        *(float4*)(yp + 4) = o1;
    }
}

__global__ void __launch_bounds__(256, 2)
qkv_kernel(const float* __restrict__ q, const float* __restrict__ k,
           const float* __restrict__ v, const float* __restrict__ Wq,
           const float* __restrict__ Wk, const float* __restrict__ Wv)
{
    const int z = blockIdx.z;
    const float* X = (z == 0) ? q : (z == 1) ? k : v;
    const float* W = (z == 0) ? Wq : (z == 1) ? Wk : Wv;
    float* Y = (z == 0) ? g_Q : (z == 1) ? g_K : g_V;
    gemm_nt_tile(X, W, nullptr, Y);
}

__global__ void __launch_bounds__(256, 2)
oproj_kernel(const float* __restrict__ Wo, const float* __restrict__ bo,
             float* __restrict__ out)
{
    gemm_nt_tile(g_C, Wo, bo, out);
}

/* ========================================================================
 *  Flash attention, fp32, Br=Bc=64, D=64.
 *  grid = (SEQ/64, BATCH*NHEAD), 256 threads.
 *  Thread (ty=tid/16, tx=tid%16) owns rows ty*4..+3 and cols tx*4..+3.
 *  Row stats kept redundantly in registers per 16-lane half-warp
 *  (rows of a 4-row group are owned by exactly one half-warp).
 * ======================================================================== */
#define APAD 68
#define ATTN_SMEM (4 * 64 * APAD * 4)   /* Qt, Kt, Vs, Ps : 69632 B */

__global__ void __launch_bounds__(256)
attn_kernel(const int* __restrict__ mask)
{
    extern __shared__ __align__(16) float sm[];
    float* Qt = sm;                   /* [64][APAD]  Qt[d][r] */
    float* Kt = sm + 64 * APAD;       /* [64][APAD]  Kt[d][c] */
    float* Vs = sm + 2 * 64 * APAD;   /* [64][APAD]  Vs[c][d] */
    float* Ps = sm + 3 * 64 * APAD;   /* [64][APAD]  Ps[r][c] */

    const int tid = threadIdx.x;
    const int bh  = blockIdx.y;
    const int b   = bh >> 4;
    const int h   = bh & 15;
    const int q0  = blockIdx.x * 64;

    const int tx = tid & 15;
    const int ty = tid >> 4;
    const int r0 = ty * 4;
    const int c0 = tx * 4;

    const int rr = tid >> 2;   /* 0..63, loader row  */
    const int dg = tid & 3;    /* loader float4 slot */

    /* load Q tile transposed: Qt[d][r] */
    {
        const float* qb = g_Q + ((size_t)(b * SEQ + q0)) * EMBED + h * HDIM;
#pragma unroll
        for (int p = 0; p < 4; p++) {
            int d4 = dg + 4 * p;
            float4 vq = *(const float4*)(qb + (size_t)rr * EMBED + d4 * 4);
            Qt[(d4 * 4 + 0) * APAD + rr] = vq.x;
            Qt[(d4 * 4 + 1) * APAD + rr] = vq.y;
            Qt[(d4 * 4 + 2) * APAD + rr] = vq.z;
            Qt[(d4 * 4 + 3) * APAD + rr] = vq.w;
        }
    }

    unsigned long long o2[4][2];
#pragma unroll
    for (int i = 0; i < 4; i++) { o2[i][0] = 0ull; o2[i][1] = 0ull; }

    float mrow[4], lrow[4];
#pragma unroll
    for (int i = 0; i < 4; i++) { mrow[i] = __int_as_float(0xff800000); lrow[i] = 0.f; }

    const float* kb = g_K + ((size_t)(b * SEQ)) * EMBED + h * HDIM;
    const float* vb = g_V + ((size_t)(b * SEQ)) * EMBED + h * HDIM;
    const unsigned long long SC2 = pk2(0.03125f, 0.03125f);  /* 1/sqrt(1024) */

    for (int ct = 0; ct < SEQ; ct += 64) {
        __syncthreads();   /* prev PV done before overwriting Kt/Vs/Ps */

        /* load K transposed + V natural */
#pragma unroll
        for (int p = 0; p < 4; p++) {
            int d4 = dg + 4 * p;
            float4 vk = *(const float4*)(kb + (size_t)(ct + rr) * EMBED + d4 * 4);
            Kt[(d4 * 4 + 0) * APAD + rr] = vk.x;
            Kt[(d4 * 4 + 1) * APAD + rr] = vk.y;
            Kt[(d4 * 4 + 2) * APAD + rr] = vk.z;
            Kt[(d4 * 4 + 3) * APAD + rr] = vk.w;
            float4 vv = *(const float4*)(vb + (size_t)(ct + rr) * EMBED + d4 * 4);
            *(float4*)&Vs[rr * APAD + d4 * 4] = vv;
        }
        __syncthreads();

        /* scores S = Q K^T (f32x2) */
        unsigned long long s2[4][2];
#pragma unroll
        for (int i = 0; i < 4; i++) { s2[i][0] = 0ull; s2[i][1] = 0ull; }

#pragma unroll 8
        for (int kk = 0; kk < HDIM; kk++) {
            float4 a = *(const float4*)&Qt[kk * APAD + r0];
            ulonglong2 bv = *(const ulonglong2*)&Kt[kk * APAD + c0];
            float av[4] = {a.x, a.y, a.z, a.w};
#pragma unroll
            for (int i = 0; i < 4; i++) {
                unsigned long long ad = pk2(av[i], av[i]);
                fma2(s2[i][0], ad, bv.x);
                fma2(s2[i][1], ad, bv.y);
            }
        }

        /* scale + unpack + mask */
        float s[4][4];
#pragma unroll
        for (int i = 0; i < 4; i++) {
            mul2(s2[i][0], SC2);
            mul2(s2[i][1], SC2);
            float2 lo = up2(s2[i][0]), hi = up2(s2[i][1]);
            s[i][0] = lo.x; s[i][1] = lo.y; s[i][2] = hi.x; s[i][3] = hi.y;
        }
#pragma unroll
        for (int i = 0; i < 4; i++) {
            int4 mk = *(const int4*)(mask + (size_t)(q0 + r0 + i) * SEQ + ct + c0);
            if (mk.x == 0) s[i][0] = NEGV;
            if (mk.y == 0) s[i][1] = NEGV;
            if (mk.z == 0) s[i][2] = NEGV;
            if (mk.w == 0) s[i][3] = NEGV;
        }

        /* online softmax: row max via half-warp butterfly */
        float fsc[4], mnew[4];
#pragma unroll
        for (int i = 0; i < 4; i++) {
            float rm = fmaxf(fmaxf(s[i][0], s[i][1]), fmaxf(s[i][2], s[i][3]));
#pragma unroll
            for (int off = 1; off < 16; off <<= 1)
                rm = fmaxf(rm, __shfl_xor_sync(0xffffffffu, rm, off, 16));
            mnew[i] = fmaxf(mrow[i], rm);
            fsc[i]  = __expf(mrow[i] - mnew[i]);
            mrow[i] = mnew[i];
        }

        /* exp, row sum, store P, rescale O */
#pragma unroll
        for (int i = 0; i < 4; i++) {
            float p0 = __expf(s[i][0] - mnew[i]);
            float p1 = __expf(s[i][1] - mnew[i]);
            float p2 = __expf(s[i][2] - mnew[i]);
            float p3 = __expf(s[i][3] - mnew[i]);
            float ps = (p0 + p1) + (p2 + p3);
#pragma unroll
            for (int off = 1; off < 16; off <<= 1)
                ps += __shfl_xor_sync(0xffffffffu, ps, off, 16);
            lrow[i] = lrow[i] * fsc[i] + ps;
            *(float4*)&Ps[(r0 + i) * APAD + c0] = make_float4(p0, p1, p2, p3);
            unsigned long long fd = pk2(fsc[i], fsc[i]);
            mul2(o2[i][0], fd);
            mul2(o2[i][1], fd);
        }
        __syncthreads();

        /* O += P V (f32x2); d-columns reuse c0 mapping */
#pragma unroll 8
        for (int c = 0; c < 64; c++) {
            ulonglong2 vv = *(const ulonglong2*)&Vs[c * APAD + c0];
#pragma unroll
            for (int i = 0; i < 4; i++) {
                float pv = Ps[(r0 + i) * APAD + c];
                unsigned long long pd = pk2(pv, pv);
                fma2(o2[i][0], pd, vv.x);
                fma2(o2[i][1], pd, vv.y);
            }
        }
    }

    /* normalize + write context [b, q, h*64 + d] */
    float* cb = g_C + ((size_t)(b * SEQ + q0)) * EMBED + h * HDIM;
#pragma unroll
    for (int i = 0; i < 4; i++) {
        float inv = 1.0f / lrow[i];
        float2 lo = up2(o2[i][0]), hi = up2(o2[i][1]);
        float4 o = make_float4(lo.x * inv, lo.y * inv, hi.x * inv, hi.y * inv);
        *(float4*)(cb + (size_t)(r0 + i) * EMBED + c0) = o;
    }
}

/* ========================================================================= */
extern "C" void kernel_launch(void* const* d_in, const int* in_sizes, int n_in,
                              void* d_out, int out_size)
{
    (void)in_sizes; (void)n_in; (void)out_size;
    const float* q    = (const float*)d_in[0];
    const float* k    = (const float*)d_in[1];
    const float* v    = (const float*)d_in[2];
    const int*   mask = (const int*)  d_in[3];
    const float* Wq   = (const float*)d_in[4];
    const float* Wk   = (const float*)d_in[5];
    const float* Wv   = (const float*)d_in[6];
    const float* Wo   = (const float*)d_in[7];
    const float* bo   = (const float*)d_in[8];
    float* out = (float*)d_out;

    /* idempotent, not a stream op — safe under graph capture */
    cudaFuncSetAttribute(attn_kernel,
                         cudaFuncAttributeMaxDynamicSharedMemorySize, ATTN_SMEM);

    dim3 gq(EMBED / 128, MROWS / 128, 3);        /* 8 x 32 x 3 */
    qkv_kernel<<<gq, 256>>>(q, k, v, Wq, Wk, Wv);

    dim3 ga(SEQ / 64, BATCH * NHEAD);            /* 32 x 32 */
    attn_kernel<<<ga, 256, ATTN_SMEM>>>(mask);

    dim3 go(EMBED / 128, MROWS / 128);           /* 8 x 32 */
    oproj_kernel<<<go, 256>>>(Wo, bo, out);
}

// round 7
// speedup vs baseline: 1.0407x; 1.0407x over previous
#include <cuda_runtime.h>

#define EMBED 1024
#define NHEAD 16
#define HDIM  64
#define BATCH 2
#define SEQ   2048
#define MROWS (BATCH*SEQ)   /* 4096 */
#define NEGV  (-1e20f)

/* ------------ scratch (device globals; no allocation allowed) ------------ */
__device__ float g_Q[MROWS*EMBED];
__device__ float g_K[MROWS*EMBED];
__device__ float g_V[MROWS*EMBED];
__device__ float g_C[MROWS*EMBED];

/* ------------ packed f32x2 helpers (FFMA2 path, bit-exact fp32) ---------- */
__device__ __forceinline__ unsigned long long pk2(float lo, float hi) {
    unsigned long long r;
    asm("mov.b64 %0, {%1,%2};" : "=l"(r) : "f"(lo), "f"(hi));
    return r;
}
__device__ __forceinline__ void fma2(unsigned long long& d,
                                     unsigned long long a, unsigned long long b) {
    asm("fma.rn.f32x2 %0, %1, %2, %0;" : "+l"(d) : "l"(a), "l"(b));
}
__device__ __forceinline__ void mul2(unsigned long long& d, unsigned long long a) {
    asm("mul.rn.f32x2 %0, %0, %1;" : "+l"(d) : "l"(a));
}
__device__ __forceinline__ float2 up2(unsigned long long v) {
    float2 f;
    asm("mov.b64 {%0,%1}, %2;" : "=f"(f.x), "=f"(f.y) : "l"(v));
    return f;
}

/* ========================================================================
 *  NT GEMM: Y[m,n] = sum_k X[m,k] * W[n,k] (+ bias[n])
 *  BM=BN=128, BK=32, 256 threads.
 *  Split-strip 8x8 thread tile: rows {ty*4, 64+ty*4}, cols {tx*4, 64+tx*4}
 *  -> all inner-loop LDS are stride-16B contiguous => bank-conflict-free.
 * ======================================================================== */
#define BKg  32
#define GPAD 132

__device__ __forceinline__ void gemm_nt_tile(const float* __restrict__ X,
                                             const float* __restrict__ W,
                                             const float* __restrict__ bias,
                                             float* __restrict__ Y)
{
    __shared__ __align__(16) float As[BKg][GPAD];   /* As[k][m] */
    __shared__ __align__(16) float Bs[BKg][GPAD];   /* Bs[k][n] */

    const int tid = threadIdx.x;
    const int m0  = blockIdx.y * 128;
    const int n0  = blockIdx.x * 128;
    const int lr  = tid >> 3;          /* 0..31 */
    const int lc  = (tid & 7) << 2;    /* 0,4,..,28 */
    const int tx  = tid & 15;
    const int ty  = tid >> 4;

    unsigned long long acc[8][4];
#pragma unroll
    for (int i = 0; i < 8; i++)
#pragma unroll
        for (int j = 0; j < 4; j++) acc[i][j] = 0ull;

    for (int k0 = 0; k0 < EMBED; k0 += BKg) {
        __syncthreads();
#pragma unroll
        for (int p = 0; p < 4; p++) {
            int m = lr + p * 32;
            float4 vx = *(const float4*)(X + (size_t)(m0 + m) * EMBED + k0 + lc);
            As[lc + 0][m] = vx.x; As[lc + 1][m] = vx.y;
            As[lc + 2][m] = vx.z; As[lc + 3][m] = vx.w;
            float4 vw = *(const float4*)(W + (size_t)(n0 + m) * EMBED + k0 + lc);
            Bs[lc + 0][m] = vw.x; Bs[lc + 1][m] = vw.y;
            Bs[lc + 2][m] = vw.z; Bs[lc + 3][m] = vw.w;
        }
        __syncthreads();

#pragma unroll 8
        for (int kk = 0; kk < BKg; kk++) {
            float4 a0 = *(const float4*)&As[kk][ty * 4];
            float4 a1 = *(const float4*)&As[kk][64 + ty * 4];
            ulonglong2 b0 = *(const ulonglong2*)&Bs[kk][tx * 4];
            ulonglong2 b1 = *(const ulonglong2*)&Bs[kk][64 + tx * 4];
            float av[8] = {a0.x, a0.y, a0.z, a0.w, a1.x, a1.y, a1.z, a1.w};
#pragma unroll
            for (int i = 0; i < 8; i++) {
                unsigned long long ad = pk2(av[i], av[i]);
                fma2(acc[i][0], ad, b0.x);
                fma2(acc[i][1], ad, b0.y);
                fma2(acc[i][2], ad, b1.x);
                fma2(acc[i][3], ad, b1.y);
            }
        }
    }

    const int nA = n0 + tx * 4;
    const int nB = n0 + 64 + tx * 4;
    float4 bbA = make_float4(0.f, 0.f, 0.f, 0.f);
    float4 bbB = bbA;
    if (bias) {
        bbA = *(const float4*)(bias + nA);
        bbB = *(const float4*)(bias + nB);
    }
#pragma unroll
    for (int i = 0; i < 8; i++) {
        int row = m0 + ((i < 4) ? (ty * 4 + i) : (64 + ty * 4 + (i - 4)));
        float2 c0 = up2(acc[i][0]), c1 = up2(acc[i][1]);
        float2 c2 = up2(acc[i][2]), c3 = up2(acc[i][3]);
        float4 o0 = make_float4(c0.x + bbA.x, c0.y + bbA.y, c1.x + bbA.z, c1.y + bbA.w);
        float4 o1 = make_float4(c2.x + bbB.x, c2.y + bbB.y, c3.x + bbB.z, c3.y + bbB.w);
        float* yp = Y + (size_t)row * EMBED;
        *(float4*)(yp + nA) = o0;
        *(float4*)(yp + nB) = o1;
    }
}

__global__ void __launch_bounds__(256, 2)
qkv_kernel(const float* __restrict__ q, const float* __restrict__ k,
           const float* __restrict__ v, const float* __restrict__ Wq,
           const float* __restrict__ Wk, const float* __restrict__ Wv)
{
    const int z = blockIdx.z;
    const float* X = (z == 0) ? q : (z == 1) ? k : v;
    const float* W = (z == 0) ? Wq : (z == 1) ? Wk : Wv;
    float* Y = (z == 0) ? g_Q : (z == 1) ? g_K : g_V;
    gemm_nt_tile(X, W, nullptr, Y);
}

__global__ void __launch_bounds__(256, 2)
oproj_kernel(const float* __restrict__ Wo, const float* __restrict__ bo,
             float* __restrict__ out)
{
    gemm_nt_tile(g_C, Wo, bo, out);
}

/* ========================================================================
 *  Flash attention, fp32, Br=Bc=64, D=64.
 *  grid = (SEQ/64, BATCH*NHEAD), 256 threads.
 *  Thread (ty=tid/16, tx=tid%16) owns rows ty*4..+3 and cols tx*4..+3.
 *  1/sqrt(EMBED) folded into Q at smem load. K/V/mask loads software-
 *  prefetched into registers to overlap with compute phases.
 * ======================================================================== */
#define APAD 68
#define ATTN_SMEM (4 * 64 * APAD * 4)   /* Qt, Kt, Vs, Ps : 69632 B */

__global__ void __launch_bounds__(256)
attn_kernel(const int* __restrict__ mask)
{
    extern __shared__ __align__(16) float sm[];
    float* Qt = sm;                   /* [64][APAD]  Qt[d][r] */
    float* Kt = sm + 64 * APAD;       /* [64][APAD]  Kt[d][c] */
    float* Vs = sm + 2 * 64 * APAD;   /* [64][APAD]  Vs[c][d] */
    float* Ps = sm + 3 * 64 * APAD;   /* [64][APAD]  Ps[r][c] */

    const int tid = threadIdx.x;
    const int bh  = blockIdx.y;
    const int b   = bh >> 4;
    const int h   = bh & 15;
    const int q0  = blockIdx.x * 64;

    const int tx = tid & 15;
    const int ty = tid >> 4;
    const int r0 = ty * 4;
    const int c0 = tx * 4;

    const int rr = tid >> 2;   /* 0..63, loader row  */
    const int dg = tid & 3;    /* loader float4 slot */

    const float* kb = g_K + ((size_t)(b * SEQ)) * EMBED + h * HDIM;
    const float* vb = g_V + ((size_t)(b * SEQ)) * EMBED + h * HDIM;

    /* load Q tile transposed (scale folded in): Qt[d][r] */
    {
        const float* qb = g_Q + ((size_t)(b * SEQ + q0)) * EMBED + h * HDIM;
        const float sc = 0.03125f;   /* 1/sqrt(1024) */
#pragma unroll
        for (int p = 0; p < 4; p++) {
            int d4 = dg + 4 * p;
            float4 vq = *(const float4*)(qb + (size_t)rr * EMBED + d4 * 4);
            Qt[(d4 * 4 + 0) * APAD + rr] = vq.x * sc;
            Qt[(d4 * 4 + 1) * APAD + rr] = vq.y * sc;
            Qt[(d4 * 4 + 2) * APAD + rr] = vq.z * sc;
            Qt[(d4 * 4 + 3) * APAD + rr] = vq.w * sc;
        }
    }

    unsigned long long o2[4][2];
#pragma unroll
    for (int i = 0; i < 4; i++) { o2[i][0] = 0ull; o2[i][1] = 0ull; }

    float mrow[4], lrow[4];
#pragma unroll
    for (int i = 0; i < 4; i++) { mrow[i] = __int_as_float(0xff800000); lrow[i] = 0.f; }

    /* prefetch tile 0 K/V into registers */
    float4 kreg[4], vreg[4];
#pragma unroll
    for (int p = 0; p < 4; p++) {
        int d4 = dg + 4 * p;
        kreg[p] = *(const float4*)(kb + (size_t)rr * EMBED + d4 * 4);
        vreg[p] = *(const float4*)(vb + (size_t)rr * EMBED + d4 * 4);
    }

    for (int ct = 0; ct < SEQ; ct += 64) {
        __syncthreads();   /* prev PV done before overwriting Kt/Vs/Ps */

        /* commit prefetched K (transposed) + V (natural) to smem */
#pragma unroll
        for (int p = 0; p < 4; p++) {
            int d4 = dg + 4 * p;
            Kt[(d4 * 4 + 0) * APAD + rr] = kreg[p].x;
            Kt[(d4 * 4 + 1) * APAD + rr] = kreg[p].y;
            Kt[(d4 * 4 + 2) * APAD + rr] = kreg[p].z;
            Kt[(d4 * 4 + 3) * APAD + rr] = kreg[p].w;
            *(float4*)&Vs[rr * APAD + d4 * 4] = vreg[p];
        }

        /* prefetch mask tile for this iteration (overlaps QK latency) */
        int4 mk[4];
#pragma unroll
        for (int i = 0; i < 4; i++)
            mk[i] = *(const int4*)(mask + (size_t)(q0 + r0 + i) * SEQ + ct + c0);

        __syncthreads();

        /* scores S = Q K^T (f32x2); scale pre-folded into Q */
        unsigned long long s2[4][2];
#pragma unroll
        for (int i = 0; i < 4; i++) { s2[i][0] = 0ull; s2[i][1] = 0ull; }

#pragma unroll 8
        for (int kk = 0; kk < HDIM; kk++) {
            float4 a = *(const float4*)&Qt[kk * APAD + r0];
            ulonglong2 bv = *(const ulonglong2*)&Kt[kk * APAD + c0];
            float av[4] = {a.x, a.y, a.z, a.w};
#pragma unroll
            for (int i = 0; i < 4; i++) {
                unsigned long long ad = pk2(av[i], av[i]);
                fma2(s2[i][0], ad, bv.x);
                fma2(s2[i][1], ad, bv.y);
            }
        }

        /* unpack + mask */
        float s[4][4];
#pragma unroll
        for (int i = 0; i < 4; i++) {
            float2 lo = up2(s2[i][0]), hi = up2(s2[i][1]);
            s[i][0] = (mk[i].x == 0) ? NEGV : lo.x;
            s[i][1] = (mk[i].y == 0) ? NEGV : lo.y;
            s[i][2] = (mk[i].z == 0) ? NEGV : hi.x;
            s[i][3] = (mk[i].w == 0) ? NEGV : hi.y;
        }

        /* online softmax: row max via half-warp butterfly */
        float fsc[4], mnew[4];
#pragma unroll
        for (int i = 0; i < 4; i++) {
            float rm = fmaxf(fmaxf(s[i][0], s[i][1]), fmaxf(s[i][2], s[i][3]));
#pragma unroll
            for (int off = 1; off < 16; off <<= 1)
                rm = fmaxf(rm, __shfl_xor_sync(0xffffffffu, rm, off, 16));
            mnew[i] = fmaxf(mrow[i], rm);
            fsc[i]  = __expf(mrow[i] - mnew[i]);
            mrow[i] = mnew[i];
        }

        /* exp, row sum, store P, rescale O */
#pragma unroll
        for (int i = 0; i < 4; i++) {
            float p0 = __expf(s[i][0] - mnew[i]);
            float p1 = __expf(s[i][1] - mnew[i]);
            float p2 = __expf(s[i][2] - mnew[i]);
            float p3 = __expf(s[i][3] - mnew[i]);
            float ps = (p0 + p1) + (p2 + p3);
#pragma unroll
            for (int off = 1; off < 16; off <<= 1)
                ps += __shfl_xor_sync(0xffffffffu, ps, off, 16);
            lrow[i] = lrow[i] * fsc[i] + ps;
            *(float4*)&Ps[(r0 + i) * APAD + c0] = make_float4(p0, p1, p2, p3);
            unsigned long long fd = pk2(fsc[i], fsc[i]);
            mul2(o2[i][0], fd);
            mul2(o2[i][1], fd);
        }
        __syncthreads();

        /* prefetch next tile K/V (overlaps the PV phase) */
        if (ct + 64 < SEQ) {
#pragma unroll
            for (int p = 0; p < 4; p++) {
                int d4 = dg + 4 * p;
                kreg[p] = *(const float4*)(kb + (size_t)(ct + 64 + rr) * EMBED + d4 * 4);
                vreg[p] = *(const float4*)(vb + (size_t)(ct + 64 + rr) * EMBED + d4 * 4);
            }
        }

        /* O += P V (f32x2); d-columns reuse c0 mapping */
#pragma unroll 8
        for (int c = 0; c < 64; c++) {
            ulonglong2 vv = *(const ulonglong2*)&Vs[c * APAD + c0];
#pragma unroll
            for (int i = 0; i < 4; i++) {
                float pv = Ps[(r0 + i) * APAD + c];
                unsigned long long pd = pk2(pv, pv);
                fma2(o2[i][0], pd, vv.x);
                fma2(o2[i][1], pd, vv.y);
            }
        }
    }

    /* normalize + write context [b, q, h*64 + d] */
    float* cb = g_C + ((size_t)(b * SEQ + q0)) * EMBED + h * HDIM;
#pragma unroll
    for (int i = 0; i < 4; i++) {
        float inv = 1.0f / lrow[i];
        float2 lo = up2(o2[i][0]), hi = up2(o2[i][1]);
        float4 o = make_float4(lo.x * inv, lo.y * inv, hi.x * inv, hi.y * inv);
        *(float4*)(cb + (size_t)(r0 + i) * EMBED + c0) = o;
    }
}

/* ========================================================================= */
extern "C" void kernel_launch(void* const* d_in, const int* in_sizes, int n_in,
                              void* d_out, int out_size)
{
    (void)in_sizes; (void)n_in; (void)out_size;
    const float* q    = (const float*)d_in[0];
    const float* k    = (const float*)d_in[1];
    const float* v    = (const float*)d_in[2];
    const int*   mask = (const int*)  d_in[3];
    const float* Wq   = (const float*)d_in[4];
    const float* Wk   = (const float*)d_in[5];
    const float* Wv   = (const float*)d_in[6];
    const float* Wo   = (const float*)d_in[7];
    const float* bo   = (const float*)d_in[8];
    float* out = (float*)d_out;

    /* idempotent, not a stream op — safe under graph capture */
    cudaFuncSetAttribute(attn_kernel,
                         cudaFuncAttributeMaxDynamicSharedMemorySize, ATTN_SMEM);

    dim3 gq(EMBED / 128, MROWS / 128, 3);        /* 8 x 32 x 3 */
    qkv_kernel<<<gq, 256>>>(q, k, v, Wq, Wk, Wv);

    dim3 ga(SEQ / 64, BATCH * NHEAD);            /* 32 x 32 */
    attn_kernel<<<ga, 256, ATTN_SMEM>>>(mask);

    dim3 go(EMBED / 128, MROWS / 128);           /* 8 x 32 */
    oproj_kernel<<<go, 256>>>(Wo, bo, out);
}

// round 10
// speedup vs baseline: 1.0582x; 1.0168x over previous
#include <cuda_runtime.h>

#define EMBED 1024
#define NHEAD 16
#define HDIM  64
#define BATCH 2
#define SEQ   2048
#define MROWS (BATCH*SEQ)   /* 4096 */
#define NEGV  (-1e20f)

/* ------------ scratch (device globals; no allocation allowed) ------------ */
__device__ float g_Q[MROWS*EMBED];
__device__ float g_K[MROWS*EMBED];
__device__ float g_V[MROWS*EMBED];
__device__ float g_C[MROWS*EMBED];

/* ------------ packed f32x2 helpers (FFMA2 path, bit-exact fp32) ---------- */
__device__ __forceinline__ unsigned long long pk2(float lo, float hi) {
    unsigned long long r;
    asm("mov.b64 %0, {%1,%2};" : "=l"(r) : "f"(lo), "f"(hi));
    return r;
}
__device__ __forceinline__ void fma2(unsigned long long& d,
                                     unsigned long long a, unsigned long long b) {
    asm("fma.rn.f32x2 %0, %1, %2, %0;" : "+l"(d) : "l"(a), "l"(b));
}
__device__ __forceinline__ void mul2(unsigned long long& d, unsigned long long a) {
    asm("mul.rn.f32x2 %0, %0, %1;" : "+l"(d) : "l"(a));
}
__device__ __forceinline__ float2 up2(unsigned long long v) {
    float2 f;
    asm("mov.b64 {%0,%1}, %2;" : "=f"(f.x), "=f"(f.y) : "l"(v));
    return f;
}

/* ========================================================================
 *  NT GEMM: Y[m,n] = sum_k X[m,k] * W[n,k] (+ bias[n])
 *  BM=BN=128, BK=16, 256 threads, DOUBLE-BUFFERED smem (1 sync / k-tile).
 *  Split-strip 8x8 thread tile: rows {ty*4, 64+ty*4}, cols {tx*4, 64+tx*4}.
 * ======================================================================== */
#define BKg  16
#define NKT  (EMBED / BKg)   /* 64 k-tiles */
#define GPAD 132

__device__ __forceinline__ void gemm_nt_tile(const float* __restrict__ X,
                                             const float* __restrict__ W,
                                             const float* __restrict__ bias,
                                             float* __restrict__ Y)
{
    __shared__ __align__(16) float As[2][BKg][GPAD];   /* As[b][k][m] */
    __shared__ __align__(16) float Bs[2][BKg][GPAD];   /* Bs[b][k][n] */

    const int tid = threadIdx.x;
    const int m0  = blockIdx.y * 128;
    const int n0  = blockIdx.x * 128;
    const int lm  = tid & 127;            /* loader row 0..127 */
    const int lk  = (tid >> 7) * 8;       /* loader k base: 0 or 8 */
    const int tx  = tid & 15;
    const int ty  = tid >> 4;

    const float* xp = X + (size_t)(m0 + lm) * EMBED + lk;
    const float* wp = W + (size_t)(n0 + lm) * EMBED + lk;

    unsigned long long acc[8][4];
#pragma unroll
    for (int i = 0; i < 8; i++)
#pragma unroll
        for (int j = 0; j < 4; j++) acc[i][j] = 0ull;

    /* prologue: tile 0 */
    {
        float4 x0 = *(const float4*)(xp);
        float4 x1 = *(const float4*)(xp + 4);
        float4 w0 = *(const float4*)(wp);
        float4 w1 = *(const float4*)(wp + 4);
        As[0][lk + 0][lm] = x0.x; As[0][lk + 1][lm] = x0.y;
        As[0][lk + 2][lm] = x0.z; As[0][lk + 3][lm] = x0.w;
        As[0][lk + 4][lm] = x1.x; As[0][lk + 5][lm] = x1.y;
        As[0][lk + 6][lm] = x1.z; As[0][lk + 7][lm] = x1.w;
        Bs[0][lk + 0][lm] = w0.x; Bs[0][lk + 1][lm] = w0.y;
        Bs[0][lk + 2][lm] = w0.z; Bs[0][lk + 3][lm] = w0.w;
        Bs[0][lk + 4][lm] = w1.x; Bs[0][lk + 5][lm] = w1.y;
        Bs[0][lk + 6][lm] = w1.z; Bs[0][lk + 7][lm] = w1.w;
    }
    __syncthreads();

#pragma unroll 1
    for (int t = 0; t < NKT; t++) {
        const int cur = t & 1;
        float4 x0, x1, w0, w1;
        const bool more = (t + 1 < NKT);
        if (more) {
            const float* xn = xp + (t + 1) * BKg;
            const float* wn = wp + (t + 1) * BKg;
            x0 = *(const float4*)(xn);
            x1 = *(const float4*)(xn + 4);
            w0 = *(const float4*)(wn);
            w1 = *(const float4*)(wn + 4);
        }

#pragma unroll
        for (int kk = 0; kk < BKg; kk++) {
            float4 a0 = *(const float4*)&As[cur][kk][ty * 4];
            float4 a1 = *(const float4*)&As[cur][kk][64 + ty * 4];
            ulonglong2 b0 = *(const ulonglong2*)&Bs[cur][kk][tx * 4];
            ulonglong2 b1 = *(const ulonglong2*)&Bs[cur][kk][64 + tx * 4];
            float av[8] = {a0.x, a0.y, a0.z, a0.w, a1.x, a1.y, a1.z, a1.w};
#pragma unroll
            for (int i = 0; i < 8; i++) {
                unsigned long long ad = pk2(av[i], av[i]);
                fma2(acc[i][0], ad, b0.x);
                fma2(acc[i][1], ad, b0.y);
                fma2(acc[i][2], ad, b1.x);
                fma2(acc[i][3], ad, b1.y);
            }
        }

        if (more) {
            const int nb = cur ^ 1;
            As[nb][lk + 0][lm] = x0.x; As[nb][lk + 1][lm] = x0.y;
            As[nb][lk + 2][lm] = x0.z; As[nb][lk + 3][lm] = x0.w;
            As[nb][lk + 4][lm] = x1.x; As[nb][lk + 5][lm] = x1.y;
            As[nb][lk + 6][lm] = x1.z; As[nb][lk + 7][lm] = x1.w;
            Bs[nb][lk + 0][lm] = w0.x; Bs[nb][lk + 1][lm] = w0.y;
            Bs[nb][lk + 2][lm] = w0.z; Bs[nb][lk + 3][lm] = w0.w;
            Bs[nb][lk + 4][lm] = w1.x; Bs[nb][lk + 5][lm] = w1.y;
            Bs[nb][lk + 6][lm] = w1.z; Bs[nb][lk + 7][lm] = w1.w;
        }
        __syncthreads();
    }

    const int nA = n0 + tx * 4;
    const int nB = n0 + 64 + tx * 4;
    float4 bbA = make_float4(0.f, 0.f, 0.f, 0.f);
    float4 bbB = bbA;
    if (bias) {
        bbA = *(const float4*)(bias + nA);
        bbB = *(const float4*)(bias + nB);
    }
#pragma unroll
    for (int i = 0; i < 8; i++) {
        int row = m0 + ((i < 4) ? (ty * 4 + i) : (64 + ty * 4 + (i - 4)));
        float2 c0 = up2(acc[i][0]), c1 = up2(acc[i][1]);
        float2 c2 = up2(acc[i][2]), c3 = up2(acc[i][3]);
        float4 o0 = make_float4(c0.x + bbA.x, c0.y + bbA.y, c1.x + bbA.z, c1.y + bbA.w);
        float4 o1 = make_float4(c2.x + bbB.x, c2.y + bbB.y, c3.x + bbB.z, c3.y + bbB.w);
        float* yp = Y + (size_t)row * EMBED;
        *(float4*)(yp + nA) = o0;
        *(float4*)(yp + nB) = o1;
    }
}

__global__ void __launch_bounds__(256, 2)
qkv_kernel(const float* __restrict__ q, const float* __restrict__ k,
           const float* __restrict__ v, const float* __restrict__ Wq,
           const float* __restrict__ Wk, const float* __restrict__ Wv)
{
    const int z = blockIdx.z;
    const float* X = (z == 0) ? q : (z == 1) ? k : v;
    const float* W = (z == 0) ? Wq : (z == 1) ? Wk : Wv;
    float* Y = (z == 0) ? g_Q : (z == 1) ? g_K : g_V;
    gemm_nt_tile(X, W, nullptr, Y);
}

__global__ void __launch_bounds__(256, 2)
oproj_kernel(const float* __restrict__ Wo, const float* __restrict__ bo,
             float* __restrict__ out)
{
    gemm_nt_tile(g_C, Wo, bo, out);
}

/* ========================================================================
 *  Flash attention, fp32, Br=128, Bc=64, D=64.
 *  grid = (SEQ/128, BATCH*NHEAD), 256 threads.
 *  Thread (ty=tid/16, tx=tid%16): rows {ty*4+i, 64+ty*4+i}, cols tx*4..+3.
 *  1/sqrt(EMBED) folded into Q. V-prefetch hidden under QK, K-prefetch
 *  hidden under PV (never co-resident -> low reg pressure).
 * ======================================================================== */
#define QT_STR 132
#define KV_STR 68
#define OFF_QT 0
#define OFF_KT (64 * QT_STR)                 /*  8448 */
#define OFF_VS (OFF_KT + 64 * KV_STR)        /* 12800 */
#define OFF_PS (OFF_VS + 64 * KV_STR)        /* 17152 */
#define ATTN_FLOATS (OFF_PS + 128 * KV_STR)  /* 25856 */
#define ATTN_SMEM (ATTN_FLOATS * 4)          /* 103424 B */

__global__ void __launch_bounds__(256, 2)
attn_kernel(const int* __restrict__ mask)
{
    extern __shared__ __align__(16) float sm[];
    float* Qt = sm + OFF_QT;    /* [64][132]  Qt[d][r], r in [0,128) */
    float* Kt = sm + OFF_KT;    /* [64][68]   Kt[d][c] */
    float* Vs = sm + OFF_VS;    /* [64][68]   Vs[c][d] */
    float* Ps = sm + OFF_PS;    /* [128][68]  Ps[r][c] */

    const int tid = threadIdx.x;
    const int bh  = blockIdx.y;
    const int b   = bh >> 4;
    const int h   = bh & 15;
    const int q0  = blockIdx.x * 128;

    const int tx = tid & 15;
    const int ty = tid >> 4;
    const int c0 = tx * 4;

    int rows[8];
#pragma unroll
    for (int j = 0; j < 8; j++)
        rows[j] = (j < 4) ? (ty * 4 + j) : (64 + ty * 4 + (j - 4));

    const int rr = tid >> 2;   /* K/V loader row 0..63 */
    const int dg = tid & 3;

    const float* kb = g_K + ((size_t)(b * SEQ)) * EMBED + h * HDIM;
    const float* vb = g_V + ((size_t)(b * SEQ)) * EMBED + h * HDIM;

    /* load Q tile transposed (scale folded): Qt[d][r], 128 rows */
    {
        const float* qb = g_Q + ((size_t)(b * SEQ + q0)) * EMBED + h * HDIM;
        const float sc = 0.03125f;   /* 1/sqrt(1024) */
        const int qrow = tid >> 1;
        const int qh   = tid & 1;
#pragma unroll
        for (int p = 0; p < 8; p++) {
            int d4 = qh * 8 + p;
            float4 vq = *(const float4*)(qb + (size_t)qrow * EMBED + d4 * 4);
            Qt[(d4 * 4 + 0) * QT_STR + qrow] = vq.x * sc;
            Qt[(d4 * 4 + 1) * QT_STR + qrow] = vq.y * sc;
            Qt[(d4 * 4 + 2) * QT_STR + qrow] = vq.z * sc;
            Qt[(d4 * 4 + 3) * QT_STR + qrow] = vq.w * sc;
        }
    }

    unsigned long long o2[8][2];
#pragma unroll
    for (int j = 0; j < 8; j++) { o2[j][0] = 0ull; o2[j][1] = 0ull; }

    float mrow[8], lrow[8];
#pragma unroll
    for (int j = 0; j < 8; j++) { mrow[j] = __int_as_float(0xff800000); lrow[j] = 0.f; }

    /* prefetch K tile 0 */
    float4 kreg[4];
#pragma unroll
    for (int p = 0; p < 4; p++) {
        int d4 = dg + 4 * p;
        kreg[p] = *(const float4*)(kb + (size_t)rr * EMBED + d4 * 4);
    }

    for (int ct = 0; ct < SEQ; ct += 64) {
        __syncthreads();   /* prev PV (Vs,Ps reads) done */

        /* commit K (transposed) */
#pragma unroll
        for (int p = 0; p < 4; p++) {
            int d4 = dg + 4 * p;
            Kt[(d4 * 4 + 0) * KV_STR + rr] = kreg[p].x;
            Kt[(d4 * 4 + 1) * KV_STR + rr] = kreg[p].y;
            Kt[(d4 * 4 + 2) * KV_STR + rr] = kreg[p].z;
            Kt[(d4 * 4 + 3) * KV_STR + rr] = kreg[p].w;
        }
        /* issue V loads for THIS tile (consumed after QK) */
        float4 vreg[4];
#pragma unroll
        for (int p = 0; p < 4; p++) {
            int d4 = dg + 4 * p;
            vreg[p] = *(const float4*)(vb + (size_t)(ct + rr) * EMBED + d4 * 4);
        }
        __syncthreads();   /* Kt ready */

        /* S = Q K^T : 8 rows x 4 cols per thread */
        unsigned long long s2[8][2];
#pragma unroll
        for (int j = 0; j < 8; j++) { s2[j][0] = 0ull; s2[j][1] = 0ull; }

#pragma unroll 8
        for (int kk = 0; kk < HDIM; kk++) {
            float4 a0 = *(const float4*)&Qt[kk * QT_STR + ty * 4];
            float4 a1 = *(const float4*)&Qt[kk * QT_STR + 64 + ty * 4];
            ulonglong2 bv = *(const ulonglong2*)&Kt[kk * KV_STR + c0];
            float av[8] = {a0.x, a0.y, a0.z, a0.w, a1.x, a1.y, a1.z, a1.w};
#pragma unroll
            for (int j = 0; j < 8; j++) {
                unsigned long long ad = pk2(av[j], av[j]);
                fma2(s2[j][0], ad, bv.x);
                fma2(s2[j][1], ad, bv.y);
            }
        }

        /* mask + softmax (online) */
#pragma unroll
        for (int j = 0; j < 8; j++) {
            int4 mk = *(const int4*)(mask + (size_t)(q0 + rows[j]) * SEQ + ct + c0);
            float2 lo = up2(s2[j][0]), hi = up2(s2[j][1]);
            float s0 = (mk.x == 0) ? NEGV : lo.x;
            float s1 = (mk.y == 0) ? NEGV : lo.y;
            float s2v = (mk.z == 0) ? NEGV : hi.x;
            float s3 = (mk.w == 0) ? NEGV : hi.y;

            float rm = fmaxf(fmaxf(s0, s1), fmaxf(s2v, s3));
#pragma unroll
            for (int off = 1; off < 16; off <<= 1)
                rm = fmaxf(rm, __shfl_xor_sync(0xffffffffu, rm, off, 16));
            float mnew = fmaxf(mrow[j], rm);
            float fsc  = __expf(mrow[j] - mnew);
            mrow[j] = mnew;

            float p0 = __expf(s0 - mnew);
            float p1 = __expf(s1 - mnew);
            float p2 = __expf(s2v - mnew);
            float p3 = __expf(s3 - mnew);
            float ps = (p0 + p1) + (p2 + p3);
#pragma unroll
            for (int off = 1; off < 16; off <<= 1)
                ps += __shfl_xor_sync(0xffffffffu, ps, off, 16);
            lrow[j] = lrow[j] * fsc + ps;
            *(float4*)&Ps[rows[j] * KV_STR + c0] = make_float4(p0, p1, p2, p3);
            unsigned long long fd = pk2(fsc, fsc);
            mul2(o2[j][0], fd);
            mul2(o2[j][1], fd);
        }

        /* commit V */
#pragma unroll
        for (int p = 0; p < 4; p++) {
            int d4 = dg + 4 * p;
            *(float4*)&Vs[rr * KV_STR + d4 * 4] = vreg[p];
        }
        __syncthreads();   /* Vs, Ps ready */

        /* prefetch next K (hidden under PV) */
        if (ct + 64 < SEQ) {
#pragma unroll
            for (int p = 0; p < 4; p++) {
                int d4 = dg + 4 * p;
                kreg[p] = *(const float4*)(kb + (size_t)(ct + 64 + rr) * EMBED + d4 * 4);
            }
        }

        /* O += P V : float4 P reads, 4 c at a time */
#pragma unroll 4
        for (int c4 = 0; c4 < 16; c4++) {
            int c = c4 * 4;
            ulonglong2 vv0 = *(const ulonglong2*)&Vs[(c + 0) * KV_STR + c0];
            ulonglong2 vv1 = *(const ulonglong2*)&Vs[(c + 1) * KV_STR + c0];
            ulonglong2 vv2 = *(const ulonglong2*)&Vs[(c + 2) * KV_STR + c0];
            ulonglong2 vv3 = *(const ulonglong2*)&Vs[(c + 3) * KV_STR + c0];
#pragma unroll
            for (int j = 0; j < 8; j++) {
                float4 p = *(const float4*)&Ps[rows[j] * KV_STR + c];
                unsigned long long pd;
                pd = pk2(p.x, p.x); fma2(o2[j][0], pd, vv0.x); fma2(o2[j][1], pd, vv0.y);
                pd = pk2(p.y, p.y); fma2(o2[j][0], pd, vv1.x); fma2(o2[j][1], pd, vv1.y);
                pd = pk2(p.z, p.z); fma2(o2[j][0], pd, vv2.x); fma2(o2[j][1], pd, vv2.y);
                pd = pk2(p.w, p.w); fma2(o2[j][0], pd, vv3.x); fma2(o2[j][1], pd, vv3.y);
            }
        }
    }

    /* normalize + write context [b, q, h*64 + d] */
    float* cb = g_C + ((size_t)(b * SEQ + q0)) * EMBED + h * HDIM;
#pragma unroll
    for (int j = 0; j < 8; j++) {
        float inv = 1.0f / lrow[j];
        float2 lo = up2(o2[j][0]), hi = up2(o2[j][1]);
        float4 o = make_float4(lo.x * inv, lo.y * inv, hi.x * inv, hi.y * inv);
        *(float4*)(cb + (size_t)rows[j] * EMBED + c0) = o;
    }
}

/* ========================================================================= */
extern "C" void kernel_launch(void* const* d_in, const int* in_sizes, int n_in,
                              void* d_out, int out_size)
{
    (void)in_sizes; (void)n_in; (void)out_size;
    const float* q    = (const float*)d_in[0];
    const float* k    = (const float*)d_in[1];
    const float* v    = (const float*)d_in[2];
    const int*   mask = (const int*)  d_in[3];
    const float* Wq   = (const float*)d_in[4];
    const float* Wk   = (const float*)d_in[5];
    const float* Wv   = (const float*)d_in[6];
    const float* Wo   = (const float*)d_in[7];
    const float* bo   = (const float*)d_in[8];
    float* out = (float*)d_out;

    /* idempotent, not a stream op — safe under graph capture */
    cudaFuncSetAttribute(attn_kernel,
                         cudaFuncAttributeMaxDynamicSharedMemorySize, ATTN_SMEM);

    dim3 gq(EMBED / 128, MROWS / 128, 3);        /* 8 x 32 x 3 */
    qkv_kernel<<<gq, 256>>>(q, k, v, Wq, Wk, Wv);

    dim3 ga(SEQ / 128, BATCH * NHEAD);           /* 16 x 32 */
    attn_kernel<<<ga, 256, ATTN_SMEM>>>(mask);

    dim3 go(EMBED / 128, MROWS / 128);           /* 8 x 32 */
    oproj_kernel<<<go, 256>>>(Wo, bo, out);
}

// round 16
// speedup vs baseline: 1.3607x; 1.2859x over previous
#include <cuda_runtime.h>
#include <cuda_bf16.h>
#include <cstdint>

#define EMBED 1024
#define NHEAD 16
#define HDIM  64
#define BATCH 2
#define SEQ   2048
#define MROWS (BATCH*SEQ)   /* 4096 */
#define NEGV  (-1e20f)

/* ------------ scratch (device globals; no allocation allowed) ------------ */
__device__ float g_Q[MROWS*EMBED];
__device__ float g_K[MROWS*EMBED];
__device__ float g_V[MROWS*EMBED];

/* bf16 hi/lo splits */
__device__ __nv_bfloat16 g_qh[MROWS*EMBED], g_ql[MROWS*EMBED];
__device__ __nv_bfloat16 g_kh[MROWS*EMBED], g_kl[MROWS*EMBED];
__device__ __nv_bfloat16 g_vh[MROWS*EMBED], g_vl[MROWS*EMBED];
__device__ __nv_bfloat16 g_ch[MROWS*EMBED], g_cl[MROWS*EMBED];
__device__ __nv_bfloat16 g_wqh[EMBED*EMBED], g_wql[EMBED*EMBED];
__device__ __nv_bfloat16 g_wkh[EMBED*EMBED], g_wkl[EMBED*EMBED];
__device__ __nv_bfloat16 g_wvh[EMBED*EMBED], g_wvl[EMBED*EMBED];
__device__ __nv_bfloat16 g_woh[EMBED*EMBED], g_wol[EMBED*EMBED];

/* ------------ packed f32x2 helpers (attention) ---------- */
__device__ __forceinline__ unsigned long long pk2(float lo, float hi) {
    unsigned long long r;
    asm("mov.b64 %0, {%1,%2};" : "=l"(r) : "f"(lo), "f"(hi));
    return r;
}
__device__ __forceinline__ void fma2(unsigned long long& d,
                                     unsigned long long a, unsigned long long b) {
    asm("fma.rn.f32x2 %0, %1, %2, %0;" : "+l"(d) : "l"(a), "l"(b));
}
__device__ __forceinline__ void mul2(unsigned long long& d, unsigned long long a) {
    asm("mul.rn.f32x2 %0, %0, %1;" : "+l"(d) : "l"(a));
}
__device__ __forceinline__ float2 up2(unsigned long long v) {
    float2 f;
    asm("mov.b64 {%0,%1}, %2;" : "=f"(f.x), "=f"(f.y) : "l"(v));
    return f;
}

__device__ __forceinline__ uint32_t smem_u32(const void* p) {
    uint32_t a;
    asm("{ .reg .u64 t; cvta.to.shared.u64 t, %1; cvt.u32.u64 %0, t; }"
        : "=r"(a) : "l"(p));
    return a;
}

/* ------------ mma.sync / ldmatrix / cp.async (baseline sm_80+ PTX) ------- */
#define LDM4(r, a) \
    asm volatile("ldmatrix.sync.aligned.m8n8.x4.shared.b16 {%0,%1,%2,%3}, [%4];" \
                 : "=r"((r)[0]), "=r"((r)[1]), "=r"((r)[2]), "=r"((r)[3]) : "r"(a))

#define MMA16816(c, a, b0, b1) \
    asm volatile("mma.sync.aligned.m16n8k16.row.col.f32.bf16.bf16.f32 " \
                 "{%0,%1,%2,%3},{%4,%5,%6,%7},{%8,%9},{%0,%1,%2,%3};" \
                 : "+f"((c)[0]), "+f"((c)[1]), "+f"((c)[2]), "+f"((c)[3]) \
                 : "r"((a)[0]), "r"((a)[1]), "r"((a)[2]), "r"((a)[3]), \
                   "r"(b0), "r"(b1))

#define CPA16(s, g) \
    asm volatile("cp.async.cg.shared.global [%0], [%1], 16;" :: "r"(s), "l"(g))
#define CPA_COMMIT()  asm volatile("cp.async.commit_group;" ::: "memory")
#define CPA_WAIT1()   asm volatile("cp.async.wait_group 1;" ::: "memory")
#define CPA_WAIT0()   asm volatile("cp.async.wait_group 0;" ::: "memory")

/* ========================================================================
 *  split: fp32 -> (bf16 hi, bf16 lo = bf16(x - hi))
 * ======================================================================== */
__global__ void split_kernel(const float* __restrict__ src,
                             __nv_bfloat16* __restrict__ hi,
                             __nv_bfloat16* __restrict__ lo, int n4)
{
    int i = blockIdx.x * blockDim.x + threadIdx.x;
    if (i >= n4) return;
    float4 v = ((const float4*)src)[i];
    __nv_bfloat16 h0 = __float2bfloat16(v.x);
    __nv_bfloat16 h1 = __float2bfloat16(v.y);
    __nv_bfloat16 h2 = __float2bfloat16(v.z);
    __nv_bfloat16 h3 = __float2bfloat16(v.w);
    __nv_bfloat16 l0 = __float2bfloat16(v.x - __bfloat162float(h0));
    __nv_bfloat16 l1 = __float2bfloat16(v.y - __bfloat162float(h1));
    __nv_bfloat16 l2 = __float2bfloat16(v.z - __bfloat162float(h2));
    __nv_bfloat16 l3 = __float2bfloat16(v.w - __bfloat162float(h3));
    __nv_bfloat162* hp = (__nv_bfloat162*)hi;
    __nv_bfloat162* lp = (__nv_bfloat162*)lo;
    hp[i*2]   = __nv_bfloat162(h0, h1);
    hp[i*2+1] = __nv_bfloat162(h2, h3);
    lp[i*2]   = __nv_bfloat162(l0, l1);
    lp[i*2+1] = __nv_bfloat162(l2, l3);
}

/* ========================================================================
 *  HMMA GEMM: Y[m,n] = sum_k A[m,k]*B[n,k] (+bias), fp32 via bf16x3.
 *  CTA 128x128, BK=32 bf16, cp.async double-buffered.
 *  8 warps (2x4), warp tile 64x32, mma.sync m16n8k16.
 *  Smem tiles stride 40 bf16 (80B) -> ldmatrix conflict-free (5r mod 8).
 * ======================================================================== */
#define SKT   40                       /* smem row stride in bf16 */
#define TILEB (128 * SKT * 2)          /* 10240 B per tile */
#define BUFB  (4 * TILEB)              /* 40960 B per buffer (Ah,Al,Bh,Bl) */
#define HG_SMEM (2 * BUFB)             /* 81920 B */
#define NTK   (EMBED / 32)             /* 32 k-tiles */

__device__ __forceinline__ void hg_prefetch(
    uint32_t sbuf, const __nv_bfloat16* Ah, const __nv_bfloat16* Al,
    const __nv_bfloat16* Bh, const __nv_bfloat16* Bl,
    int m0, int n0, int k0, int tid)
{
#pragma unroll
    for (int i = 0; i < 2; i++) {
        int c   = tid + i * 256;      /* 0..511 chunks of 16B */
        int row = c >> 2;
        int kc  = c & 3;
        uint32_t so = (uint32_t)(row * SKT * 2 + kc * 16);
        size_t gA = (size_t)(m0 + row) * EMBED + k0 + kc * 8;
        size_t gB = (size_t)(n0 + row) * EMBED + k0 + kc * 8;
        CPA16(sbuf + 0 * TILEB + so, Ah + gA);
        CPA16(sbuf + 1 * TILEB + so, Al + gA);
        CPA16(sbuf + 2 * TILEB + so, Bh + gB);
        CPA16(sbuf + 3 * TILEB + so, Bl + gB);
    }
}

__global__ void __launch_bounds__(256, 1)
hmma_gemm(const __nv_bfloat16* __restrict__ Ah, const __nv_bfloat16* __restrict__ Al,
          const __nv_bfloat16* __restrict__ Bh, const __nv_bfloat16* __restrict__ Bl,
          const float* __restrict__ bias, float* __restrict__ Y)
{
    extern __shared__ __align__(16) char smx[];
    const uint32_t sb = smem_u32(smx);
    const int tid  = threadIdx.x;
    const int lane = tid & 31;
    const int wid  = tid >> 5;
    const int wm   = wid >> 2;          /* 0..1 */
    const int wn   = wid & 3;           /* 0..3 */
    const int m0   = blockIdx.y * 128;
    const int n0   = blockIdx.x * 128;

    float acc[4][4][4];
#pragma unroll
    for (int mt = 0; mt < 4; mt++)
#pragma unroll
        for (int nt = 0; nt < 4; nt++)
#pragma unroll
            for (int f = 0; f < 4; f++) acc[mt][nt][f] = 0.f;

    /* ldmatrix byte offsets (ks=0); ks=1 adds 32B */
    uint32_t offA[4], offB[2];
#pragma unroll
    for (int mt = 0; mt < 4; mt++)
        offA[mt] = (uint32_t)(((wm * 64 + mt * 16 + ((lane >> 3) & 1) * 8 + (lane & 7)) * SKT
                               + ((lane >> 4) & 1) * 8) * 2);
#pragma unroll
    for (int p = 0; p < 2; p++)
        offB[p] = (uint32_t)(((wn * 32 + p * 16 + ((lane >> 4) & 1) * 8 + (lane & 7)) * SKT
                              + ((lane >> 3) & 1) * 8) * 2);

    hg_prefetch(sb, Ah, Al, Bh, Bl, m0, n0, 0, tid);
    CPA_COMMIT();

#pragma unroll 1
    for (int t = 0; t < NTK; t++) {
        if (t + 1 < NTK) {
            hg_prefetch(sb + ((t + 1) & 1) * BUFB, Ah, Al, Bh, Bl,
                        m0, n0, (t + 1) * 32, tid);
            CPA_COMMIT();
            CPA_WAIT1();
        } else {
            CPA_WAIT0();
        }
        __syncthreads();

        const uint32_t bA_h = sb + (t & 1) * BUFB + 0 * TILEB;
        const uint32_t bA_l = sb + (t & 1) * BUFB + 1 * TILEB;
        const uint32_t bB_h = sb + (t & 1) * BUFB + 2 * TILEB;
        const uint32_t bB_l = sb + (t & 1) * BUFB + 3 * TILEB;

#pragma unroll
        for (int ks = 0; ks < 2; ks++) {
            const uint32_t kso = ks * 32;
            uint32_t ah[4][4], bh[2][4];
#pragma unroll
            for (int mt = 0; mt < 4; mt++) LDM4(ah[mt], bA_h + offA[mt] + kso);
#pragma unroll
            for (int p = 0; p < 2; p++)    LDM4(bh[p],  bB_h + offB[p] + kso);
#pragma unroll
            for (int mt = 0; mt < 4; mt++)
#pragma unroll
                for (int nt = 0; nt < 4; nt++)
                    MMA16816(acc[mt][nt], ah[mt], bh[nt >> 1][(nt & 1) * 2],
                             bh[nt >> 1][(nt & 1) * 2 + 1]);

            uint32_t bl[2][4];
#pragma unroll
            for (int p = 0; p < 2; p++)    LDM4(bl[p],  bB_l + offB[p] + kso);
#pragma unroll
            for (int mt = 0; mt < 4; mt++)
#pragma unroll
                for (int nt = 0; nt < 4; nt++)
                    MMA16816(acc[mt][nt], ah[mt], bl[nt >> 1][(nt & 1) * 2],
                             bl[nt >> 1][(nt & 1) * 2 + 1]);

            uint32_t al[4][4];
#pragma unroll
            for (int mt = 0; mt < 4; mt++) LDM4(al[mt], bA_l + offA[mt] + kso);
#pragma unroll
            for (int mt = 0; mt < 4; mt++)
#pragma unroll
                for (int nt = 0; nt < 4; nt++)
                    MMA16816(acc[mt][nt], al[mt], bh[nt >> 1][(nt & 1) * 2],
                             bh[nt >> 1][(nt & 1) * 2 + 1]);
        }
        __syncthreads();
    }

    /* epilogue: frag (m16n8): c0,c1 @ (row=lane/4, col=(lane%4)*2); c2,c3 row+8 */
    const int er = lane >> 2;
    const int ec = (lane & 3) * 2;
#pragma unroll
    for (int mt = 0; mt < 4; mt++) {
#pragma unroll
        for (int nt = 0; nt < 4; nt++) {
            int grow = m0 + wm * 64 + mt * 16 + er;
            int gcol = n0 + wn * 32 + nt * 8 + ec;
            float b0 = 0.f, b1 = 0.f;
            if (bias) { b0 = bias[gcol]; b1 = bias[gcol + 1]; }
            float2 v0 = make_float2(acc[mt][nt][0] + b0, acc[mt][nt][1] + b1);
            float2 v1 = make_float2(acc[mt][nt][2] + b0, acc[mt][nt][3] + b1);
            *(float2*)(Y + (size_t)grow * EMBED + gcol)       = v0;
            *(float2*)(Y + (size_t)(grow + 8) * EMBED + gcol) = v1;
        }
    }
}

/* ========================================================================
 *  Flash attention, fp32, Br=128, Bc=64, D=64.  (passing R10 version;
 *  epilogue now writes bf16 hi/lo context directly)
 * ======================================================================== */
#define QT_STR 132
#define KV_STR 68
#define OFF_QT 0
#define OFF_KT (64 * QT_STR)
#define OFF_VS (OFF_KT + 64 * KV_STR)
#define OFF_PS (OFF_VS + 64 * KV_STR)
#define ATTN_FLOATS (OFF_PS + 128 * KV_STR)
#define ATTN_SMEM (ATTN_FLOATS * 4)

__global__ void __launch_bounds__(256, 2)
attn_kernel(const int* __restrict__ mask)
{
    extern __shared__ __align__(16) float sm[];
    float* Qt = sm + OFF_QT;
    float* Kt = sm + OFF_KT;
    float* Vs = sm + OFF_VS;
    float* Ps = sm + OFF_PS;

    const int tid = threadIdx.x;
    const int bh  = blockIdx.y;
    const int b   = bh >> 4;
    const int h   = bh & 15;
    const int q0  = blockIdx.x * 128;

    const int tx = tid & 15;
    const int ty = tid >> 4;
    const int c0 = tx * 4;

    int rows[8];
#pragma unroll
    for (int j = 0; j < 8; j++)
        rows[j] = (j < 4) ? (ty * 4 + j) : (64 + ty * 4 + (j - 4));

    const int rr = tid >> 2;
    const int dg = tid & 3;

    const float* kb = g_K + ((size_t)(b * SEQ)) * EMBED + h * HDIM;
    const float* vb = g_V + ((size_t)(b * SEQ)) * EMBED + h * HDIM;

    {
        const float* qb = g_Q + ((size_t)(b * SEQ + q0)) * EMBED + h * HDIM;
        const float sc = 0.03125f;
        const int qrow = tid >> 1;
        const int qh   = tid & 1;
#pragma unroll
        for (int p = 0; p < 8; p++) {
            int d4 = qh * 8 + p;
            float4 vq = *(const float4*)(qb + (size_t)qrow * EMBED + d4 * 4);
            Qt[(d4 * 4 + 0) * QT_STR + qrow] = vq.x * sc;
            Qt[(d4 * 4 + 1) * QT_STR + qrow] = vq.y * sc;
            Qt[(d4 * 4 + 2) * QT_STR + qrow] = vq.z * sc;
            Qt[(d4 * 4 + 3) * QT_STR + qrow] = vq.w * sc;
        }
    }

    unsigned long long o2[8][2];
#pragma unroll
    for (int j = 0; j < 8; j++) { o2[j][0] = 0ull; o2[j][1] = 0ull; }

    float mrow[8], lrow[8];
#pragma unroll
    for (int j = 0; j < 8; j++) { mrow[j] = __int_as_float(0xff800000); lrow[j] = 0.f; }

    float4 kreg[4];
#pragma unroll
    for (int p = 0; p < 4; p++) {
        int d4 = dg + 4 * p;
        kreg[p] = *(const float4*)(kb + (size_t)rr * EMBED + d4 * 4);
    }

    for (int ct = 0; ct < SEQ; ct += 64) {
        __syncthreads();
#pragma unroll
        for (int p = 0; p < 4; p++) {
            int d4 = dg + 4 * p;
            Kt[(d4 * 4 + 0) * KV_STR + rr] = kreg[p].x;
            Kt[(d4 * 4 + 1) * KV_STR + rr] = kreg[p].y;
            Kt[(d4 * 4 + 2) * KV_STR + rr] = kreg[p].z;
            Kt[(d4 * 4 + 3) * KV_STR + rr] = kreg[p].w;
        }
        float4 vreg[4];
#pragma unroll
        for (int p = 0; p < 4; p++) {
            int d4 = dg + 4 * p;
            vreg[p] = *(const float4*)(vb + (size_t)(ct + rr) * EMBED + d4 * 4);
        }
        __syncthreads();

        unsigned long long s2[8][2];
#pragma unroll
        for (int j = 0; j < 8; j++) { s2[j][0] = 0ull; s2[j][1] = 0ull; }

#pragma unroll 8
        for (int kk = 0; kk < HDIM; kk++) {
            float4 a0 = *(const float4*)&Qt[kk * QT_STR + ty * 4];
            float4 a1 = *(const float4*)&Qt[kk * QT_STR + 64 + ty * 4];
            ulonglong2 bv = *(const ulonglong2*)&Kt[kk * KV_STR + c0];
            float av[8] = {a0.x, a0.y, a0.z, a0.w, a1.x, a1.y, a1.z, a1.w};
#pragma unroll
            for (int j = 0; j < 8; j++) {
                unsigned long long ad = pk2(av[j], av[j]);
                fma2(s2[j][0], ad, bv.x);
                fma2(s2[j][1], ad, bv.y);
            }
        }

#pragma unroll
        for (int j = 0; j < 8; j++) {
            int4 mk = *(const int4*)(mask + (size_t)(q0 + rows[j]) * SEQ + ct + c0);
            float2 lo = up2(s2[j][0]), hi = up2(s2[j][1]);
            float s0 = (mk.x == 0) ? NEGV : lo.x;
            float s1 = (mk.y == 0) ? NEGV : lo.y;
            float s2v = (mk.z == 0) ? NEGV : hi.x;
            float s3 = (mk.w == 0) ? NEGV : hi.y;

            float rm = fmaxf(fmaxf(s0, s1), fmaxf(s2v, s3));
#pragma unroll
            for (int off = 1; off < 16; off <<= 1)
                rm = fmaxf(rm, __shfl_xor_sync(0xffffffffu, rm, off, 16));
            float mnew = fmaxf(mrow[j], rm);
            float fsc  = __expf(mrow[j] - mnew);
            mrow[j] = mnew;

            float p0 = __expf(s0 - mnew);
            float p1 = __expf(s1 - mnew);
            float p2 = __expf(s2v - mnew);
            float p3 = __expf(s3 - mnew);
            float ps = (p0 + p1) + (p2 + p3);
#pragma unroll
            for (int off = 1; off < 16; off <<= 1)
                ps += __shfl_xor_sync(0xffffffffu, ps, off, 16);
            lrow[j] = lrow[j] * fsc + ps;
            *(float4*)&Ps[rows[j] * KV_STR + c0] = make_float4(p0, p1, p2, p3);
            unsigned long long fd = pk2(fsc, fsc);
            mul2(o2[j][0], fd);
            mul2(o2[j][1], fd);
        }

#pragma unroll
        for (int p = 0; p < 4; p++) {
            int d4 = dg + 4 * p;
            *(float4*)&Vs[rr * KV_STR + d4 * 4] = vreg[p];
        }
        __syncthreads();

        if (ct + 64 < SEQ) {
#pragma unroll
            for (int p = 0; p < 4; p++) {
                int d4 = dg + 4 * p;
                kreg[p] = *(const float4*)(kb + (size_t)(ct + 64 + rr) * EMBED + d4 * 4);
            }
        }

#pragma unroll 4
        for (int c4 = 0; c4 < 16; c4++) {
            int c = c4 * 4;
            ulonglong2 vv0 = *(const ulonglong2*)&Vs[(c + 0) * KV_STR + c0];
            ulonglong2 vv1 = *(const ulonglong2*)&Vs[(c + 1) * KV_STR + c0];
            ulonglong2 vv2 = *(const ulonglong2*)&Vs[(c + 2) * KV_STR + c0];
            ulonglong2 vv3 = *(const ulonglong2*)&Vs[(c + 3) * KV_STR + c0];
#pragma unroll
            for (int j = 0; j < 8; j++) {
                float4 p = *(const float4*)&Ps[rows[j] * KV_STR + c];
                unsigned long long pd;
                pd = pk2(p.x, p.x); fma2(o2[j][0], pd, vv0.x); fma2(o2[j][1], pd, vv0.y);
                pd = pk2(p.y, p.y); fma2(o2[j][0], pd, vv1.x); fma2(o2[j][1], pd, vv1.y);
                pd = pk2(p.z, p.z); fma2(o2[j][0], pd, vv2.x); fma2(o2[j][1], pd, vv2.y);
                pd = pk2(p.w, p.w); fma2(o2[j][0], pd, vv3.x); fma2(o2[j][1], pd, vv3.y);
            }
        }
    }

    /* normalize + write context directly as bf16 hi/lo */
    __nv_bfloat16* chp = g_ch + ((size_t)(b * SEQ + q0)) * EMBED + h * HDIM;
    __nv_bfloat16* clp = g_cl + ((size_t)(b * SEQ + q0)) * EMBED + h * HDIM;
#pragma unroll
    for (int j = 0; j < 8; j++) {
        float inv = 1.0f / lrow[j];
        float2 lo = up2(o2[j][0]), hi = up2(o2[j][1]);
        float o[4] = {lo.x * inv, lo.y * inv, hi.x * inv, hi.y * inv};
        __nv_bfloat16 hh[4], ll[4];
#pragma unroll
        for (int e = 0; e < 4; e++) {
            hh[e] = __float2bfloat16(o[e]);
            ll[e] = __float2bfloat16(o[e] - __bfloat162float(hh[e]));
        }
        size_t off = (size_t)rows[j] * EMBED + c0;
        *(__nv_bfloat162*)(chp + off)     = __nv_bfloat162(hh[0], hh[1]);
        *(__nv_bfloat162*)(chp + off + 2) = __nv_bfloat162(hh[2], hh[3]);
        *(__nv_bfloat162*)(clp + off)     = __nv_bfloat162(ll[0], ll[1]);
        *(__nv_bfloat162*)(clp + off + 2) = __nv_bfloat162(ll[2], ll[3]);
    }
}

/* ========================================================================= */
extern "C" void kernel_launch(void* const* d_in, const int* in_sizes, int n_in,
                              void* d_out, int out_size)
{
    (void)in_sizes; (void)n_in; (void)out_size;
    const float* q    = (const float*)d_in[0];
    const float* k    = (const float*)d_in[1];
    const float* v    = (const float*)d_in[2];
    const int*   mask = (const int*)  d_in[3];
    const float* Wq   = (const float*)d_in[4];
    const float* Wk   = (const float*)d_in[5];
    const float* Wv   = (const float*)d_in[6];
    const float* Wo   = (const float*)d_in[7];
    const float* bo   = (const float*)d_in[8];
    float* out = (float*)d_out;

    cudaFuncSetAttribute(attn_kernel,
                         cudaFuncAttributeMaxDynamicSharedMemorySize, ATTN_SMEM);
    cudaFuncSetAttribute(hmma_gemm,
                         cudaFuncAttributeMaxDynamicSharedMemorySize, HG_SMEM);

    static void *p_qh=0,*p_ql=0,*p_kh=0,*p_kl=0,*p_vh=0,*p_vl=0,*p_ch=0,*p_cl=0;
    static void *p_wqh=0,*p_wql=0,*p_wkh=0,*p_wkl=0,*p_wvh=0,*p_wvl=0,*p_woh=0,*p_wol=0;
    static void *p_Q=0,*p_K=0,*p_V=0;
    if (!p_qh) {
        cudaGetSymbolAddress(&p_qh, g_qh);  cudaGetSymbolAddress(&p_ql, g_ql);
        cudaGetSymbolAddress(&p_kh, g_kh);  cudaGetSymbolAddress(&p_kl, g_kl);
        cudaGetSymbolAddress(&p_vh, g_vh);  cudaGetSymbolAddress(&p_vl, g_vl);
        cudaGetSymbolAddress(&p_ch, g_ch);  cudaGetSymbolAddress(&p_cl, g_cl);
        cudaGetSymbolAddress(&p_wqh, g_wqh); cudaGetSymbolAddress(&p_wql, g_wql);
        cudaGetSymbolAddress(&p_wkh, g_wkh); cudaGetSymbolAddress(&p_wkl, g_wkl);
        cudaGetSymbolAddress(&p_wvh, g_wvh); cudaGetSymbolAddress(&p_wvl, g_wvl);
        cudaGetSymbolAddress(&p_woh, g_woh); cudaGetSymbolAddress(&p_wol, g_wol);
        cudaGetSymbolAddress(&p_Q, g_Q); cudaGetSymbolAddress(&p_K, g_K);
        cudaGetSymbolAddress(&p_V, g_V);
    }

    const int n4a = MROWS * EMBED / 4;
    const int n4w = EMBED * EMBED / 4;
    split_kernel<<<(n4a + 255) / 256, 256>>>(q, (__nv_bfloat16*)p_qh, (__nv_bfloat16*)p_ql, n4a);
    split_kernel<<<(n4a + 255) / 256, 256>>>(k, (__nv_bfloat16*)p_kh, (__nv_bfloat16*)p_kl, n4a);
    split_kernel<<<(n4a + 255) / 256, 256>>>(v, (__nv_bfloat16*)p_vh, (__nv_bfloat16*)p_vl, n4a);
    split_kernel<<<(n4w + 255) / 256, 256>>>(Wq, (__nv_bfloat16*)p_wqh, (__nv_bfloat16*)p_wql, n4w);
    split_kernel<<<(n4w + 255) / 256, 256>>>(Wk, (__nv_bfloat16*)p_wkh, (__nv_bfloat16*)p_wkl, n4w);
    split_kernel<<<(n4w + 255) / 256, 256>>>(Wv, (__nv_bfloat16*)p_wvh, (__nv_bfloat16*)p_wvl, n4w);
    split_kernel<<<(n4w + 255) / 256, 256>>>(Wo, (__nv_bfloat16*)p_woh, (__nv_bfloat16*)p_wol, n4w);

    dim3 gg(EMBED / 128, MROWS / 128);   /* 8 x 32 */
    hmma_gemm<<<gg, 256, HG_SMEM>>>((__nv_bfloat16*)p_qh, (__nv_bfloat16*)p_ql,
                                    (__nv_bfloat16*)p_wqh, (__nv_bfloat16*)p_wql,
                                    nullptr, (float*)p_Q);
    hmma_gemm<<<gg, 256, HG_SMEM>>>((__nv_bfloat16*)p_kh, (__nv_bfloat16*)p_kl,
                                    (__nv_bfloat16*)p_wkh, (__nv_bfloat16*)p_wkl,
                                    nullptr, (float*)p_K);
    hmma_gemm<<<gg, 256, HG_SMEM>>>((__nv_bfloat16*)p_vh, (__nv_bfloat16*)p_vl,
                                    (__nv_bfloat16*)p_wvh, (__nv_bfloat16*)p_wvl,
                                    nullptr, (float*)p_V);

    dim3 ga(SEQ / 128, BATCH * NHEAD);   /* 16 x 32 */
    attn_kernel<<<ga, 256, ATTN_SMEM>>>(mask);

    hmma_gemm<<<gg, 256, HG_SMEM>>>((__nv_bfloat16*)p_ch, (__nv_bfloat16*)p_cl,
                                    (__nv_bfloat16*)p_woh, (__nv_bfloat16*)p_wol,
                                    bo, out);
}